// round 16
// baseline (speedup 1.0000x reference)
#include <cuda_runtime.h>
#include <cstdint>

#define N_NODES 50000
#define N_EDGES 800000
#define N_GRAPHS 128
#define IN_CH 31
#define C_PAD 32
#define HID 64
#define EPS_IN 1e-5f
#define LOG2E 1.4426950408889634f

#define SCAN_B 1024
#define SCAN_NB ((N_NODES + SCAN_B - 1) / SCAN_B)  // 49
#define E4 (N_EDGES / 4)                            // 200000

typedef unsigned long long u64;

// ---------------- scratch (static device globals; no allocation) ----------------
// INVARIANT: g_deg is all-zero at every kernel_launch entry (zero-init at module
// load; k_scan re-zeroes it after consuming it each run). g_syncc is zeroed by
// k_prep before k_scan uses it.
__device__ float g_xpad[N_NODES * C_PAD];
__device__ float g_bufA[N_NODES * HID];
__device__ float g_bufB[N_NODES * HID];
__device__ float g_aggr[N_NODES * HID];
__device__ int g_deg[N_NODES];
__device__ int g_rowptr[N_NODES + 1];
__device__ int g_fill[N_NODES];
__device__ int g_csr[N_EDGES];
__device__ int g_part[SCAN_NB];
__device__ int g_syncc;
__device__ unsigned g_hbits[N_GRAPHS * 3 * HID];
__device__ float g_Wl1T[(3 * HID) * (2 * HID)];
__device__ float g_Wl2T[(2 * HID) * (HID / 2)];

// ---------------- packed / fast-math helpers ----------------
__device__ __forceinline__ u64 pk2(float v) {
    u64 r;
    asm("mov.b64 %0, {%1, %1};" : "=l"(r) : "f"(v));
    return r;
}
__device__ __forceinline__ u64 ffma2(u64 a, u64 b, u64 c) {
    u64 d;
    asm("fma.rn.f32x2 %0, %1, %2, %3;" : "=l"(d) : "l"(a), "l"(b), "l"(c));
    return d;
}
__device__ __forceinline__ float2 up2(u64 v) {
    float2 f;
    asm("mov.b64 {%0, %1}, %2;" : "=f"(f.x), "=f"(f.y) : "l"(v));
    return f;
}
__device__ __forceinline__ float ex2(float x) {
    float r;
    asm("ex2.approx.f32 %0, %1;" : "=f"(r) : "f"(x));
    return r;
}

// ---------------- prep: pad x, zero hbits/sync, transpose head weights, AND hist ----
__global__ void k_prep(const float* __restrict__ x,
                       const float* __restrict__ Wl1,
                       const float* __restrict__ Wl2,
                       const int* __restrict__ dst) {
    int i = blockIdx.x * 256 + threadIdx.x;
    if (i == 0) g_syncc = 0;
    if (i < N_NODES * C_PAD) {
        int n = i >> 5, c = i & 31;
        g_xpad[i] = (c < IN_CH) ? x[n * IN_CH + c] : 0.f;
    }
    if (i < N_GRAPHS * 3 * HID / 4) {
        ((uint4*)g_hbits)[i] = make_uint4(0u, 0u, 0u, 0u);
    }
    if (i < 128 * 192) {
        int o = i / 192, c = i % 192;
        g_Wl1T[c * 128 + o] = Wl1[i];
    }
    if (i < 32 * 128) {
        int o = i / 128, c = i % 128;
        g_Wl2T[c * 32 + o] = Wl2[i];
    }
    if (i < E4) {
        int4 d = __ldg((const int4*)dst + i);
        atomicAdd(&g_deg[d.x], 1);
        atomicAdd(&g_deg[d.y], 1);
        atomicAdd(&g_deg[d.z], 1);
        atomicAdd(&g_deg[d.w], 1);
    }
}

// ---------------- single-kernel exclusive scan with software global barrier --------
// 49 blocks x 1024 threads: always co-resident on 148 SMs -> spin is safe.
__global__ void k_scan() {
    __shared__ int ws[32];
    __shared__ int soff_sh;
    int tid = threadIdx.x;
    int b = blockIdx.x;
    int lane = tid & 31, w = tid >> 5;
    int i = b * SCAN_B + tid;
    int v = (i < N_NODES) ? g_deg[i] : 0;

    // phase A: block reduce
    int r = v;
#pragma unroll
    for (int off = 16; off; off >>= 1) r += __shfl_xor_sync(0xFFFFFFFFu, r, off);
    if (lane == 0) ws[w] = r;
    __syncthreads();
    if (tid < 32) {
        int u = ws[tid];
#pragma unroll
        for (int off = 16; off; off >>= 1) u += __shfl_xor_sync(0xFFFFFFFFu, u, off);
        if (tid == 0) {
            g_part[b] = u;
            __threadfence();
            atomicAdd(&g_syncc, 1);
        }
    }
    if (tid == 0) soff_sh = 0;
    if (tid == 0) {
        while (*(volatile int*)&g_syncc < SCAN_NB) {}
    }
    __syncthreads();
    __threadfence();

    // phase B: sum of g_part[0..b-1]
    if (tid < 64) {
        int pv = (tid < b) ? g_part[tid] : 0;  // b <= 48 < 64
#pragma unroll
        for (int off = 16; off; off >>= 1) pv += __shfl_xor_sync(0xFFFFFFFFu, pv, off);
        if (lane == 0) atomicAdd(&soff_sh, pv);
    }

    // phase C: block scan (warp shfl)
    int sc = v;
#pragma unroll
    for (int off = 1; off < 32; off <<= 1) {
        int a = __shfl_up_sync(0xFFFFFFFFu, sc, off);
        if (lane >= off) sc += a;
    }
    if (lane == 31) ws[w] = sc;
    __syncthreads();
    if (tid < 32) {
        int u = ws[tid];
#pragma unroll
        for (int off = 1; off < 32; off <<= 1) {
            int a = __shfl_up_sync(0xFFFFFFFFu, u, off);
            if (tid >= off) u += a;
        }
        ws[tid] = u;
    }
    __syncthreads();
    int woff = (w > 0) ? ws[w - 1] : 0;
    if (i < N_NODES) {
        int incl = sc + woff + soff_sh;
        g_rowptr[i + 1] = incl;
        g_fill[i] = incl - v;
        g_deg[i] = 0;  // restore invariant for next run's fused hist
    }
    if (b == 0 && tid == 0) g_rowptr[0] = 0;
}

// separate scatter: 200K threads -> max ATOMG concurrency (proven faster than
// the fused 49-block variant; r15 regression)
__global__ void k_scatter(const int* __restrict__ src, const int* __restrict__ dst) {
    int e4 = blockIdx.x * 256 + threadIdx.x;
    if (e4 < E4) {
        int4 d = __ldg((const int4*)dst + e4);
        int4 sv = __ldg((const int4*)src + e4);
        int p0 = atomicAdd(&g_fill[d.x], 1);
        int p1 = atomicAdd(&g_fill[d.y], 1);
        int p2 = atomicAdd(&g_fill[d.z], 1);
        int p3 = atomicAdd(&g_fill[d.w], 1);
        g_csr[p0] = sv.x;
        g_csr[p1] = sv.y;
        g_csr[p2] = sv.z;
        g_csr[p3] = sv.w;
    }
}

// ---------------- one-pass segment softmax aggregation ----------------
// aggr[n,c] = sum_e v*exp(t*v) / sum_e exp(t*v)  (shift-invariant; logits bounded)
// aggr32: quarter-warp edge-parallel — 4 edges/step, 8 lanes per edge, float4/lane.
__global__ __launch_bounds__(256) void k_aggr32(const float* __restrict__ xin,
                                                const float* __restrict__ tptr,
                                                float* __restrict__ aggr) {
    int node = (blockIdx.x * 256 + threadIdx.x) >> 5;
    int lane = threadIdx.x & 31;
    if (node >= N_NODES) return;
    float t2 = __ldg(tptr) * LOG2E;
    int beg = g_rowptr[node];
    int end = g_rowptr[node + 1];
    int q = lane >> 3;        // quarter 0..3 -> edge k+q
    int cl = (lane & 7) * 4;  // channels cl..cl+3
    const float* xb = xin + cl;
    float4 num = make_float4(0.f, 0.f, 0.f, 0.f);
    float4 den = make_float4(0.f, 0.f, 0.f, 0.f);
    int k = beg;
#define STEP32(kk)                                                      \
    {                                                                   \
        int s = g_csr[(kk) + q];                                        \
        float4 v = *(const float4*)(xb + (size_t)s * C_PAD);            \
        float e;                                                        \
        e = ex2(v.x * t2); den.x += e; num.x = fmaf(v.x, e, num.x);     \
        e = ex2(v.y * t2); den.y += e; num.y = fmaf(v.y, e, num.y);     \
        e = ex2(v.z * t2); den.z += e; num.z = fmaf(v.z, e, num.z);     \
        e = ex2(v.w * t2); den.w += e; num.w = fmaf(v.w, e, num.w);     \
    }
    for (; k + 8 <= end; k += 8) { STEP32(k) STEP32(k + 4) }
    for (; k + 4 <= end; k += 4) STEP32(k)
#undef STEP32
    if (k < end) {  // masked tail step (1..3 edges)
        int kk = min(k + q, end - 1);
        int s = g_csr[kk];
        float m = (k + q < end) ? 1.f : 0.f;
        float4 v = *(const float4*)(xb + (size_t)s * C_PAD);
        float e;
        e = ex2(v.x * t2) * m; den.x += e; num.x = fmaf(v.x, e, num.x);
        e = ex2(v.y * t2) * m; den.y += e; num.y = fmaf(v.y, e, num.y);
        e = ex2(v.z * t2) * m; den.z += e; num.z = fmaf(v.z, e, num.z);
        e = ex2(v.w * t2) * m; den.w += e; num.w = fmaf(v.w, e, num.w);
    }
    // reduce across the 4 quarters (channel set identical per lane&7)
#pragma unroll
    for (int off = 8; off <= 16; off <<= 1) {
        num.x += __shfl_xor_sync(0xFFFFFFFFu, num.x, off);
        num.y += __shfl_xor_sync(0xFFFFFFFFu, num.y, off);
        num.z += __shfl_xor_sync(0xFFFFFFFFu, num.z, off);
        num.w += __shfl_xor_sync(0xFFFFFFFFu, num.w, off);
        den.x += __shfl_xor_sync(0xFFFFFFFFu, den.x, off);
        den.y += __shfl_xor_sync(0xFFFFFFFFu, den.y, off);
        den.z += __shfl_xor_sync(0xFFFFFFFFu, den.z, off);
        den.w += __shfl_xor_sync(0xFFFFFFFFu, den.w, off);
    }
    if (lane < 8) {
        float4 o;
        o.x = (den.x > 0.f) ? num.x / den.x : 0.f;
        o.y = (den.y > 0.f) ? num.y / den.y : 0.f;
        o.z = (den.z > 0.f) ? num.z / den.z : 0.f;
        o.w = (den.w > 0.f) ? num.w / den.w : 0.f;
        *(float4*)(aggr + (size_t)node * C_PAD + cl) = o;
    }
}

// aggr64: half-warp edge-parallel — 2 edges/step, 16 lanes per edge, float4/lane.
__global__ __launch_bounds__(256) void k_aggr64(const float* __restrict__ xin,
                                                const float* __restrict__ tptr,
                                                float* __restrict__ aggr) {
    int node = (blockIdx.x * 256 + threadIdx.x) >> 5;
    int lane = threadIdx.x & 31;
    if (node >= N_NODES) return;
    float t2 = __ldg(tptr) * LOG2E;
    int beg = g_rowptr[node];
    int end = g_rowptr[node + 1];
    int h = lane >> 4;         // half 0/1 -> edge k+h
    int cl = (lane & 15) * 4;  // channels cl..cl+3
    const float* xb = xin + cl;
    float4 num = make_float4(0.f, 0.f, 0.f, 0.f);
    float4 den = make_float4(0.f, 0.f, 0.f, 0.f);
    int k = beg;
#define STEP64(kk)                                                      \
    {                                                                   \
        int s = g_csr[(kk) + h];                                        \
        float4 v = *(const float4*)(xb + (size_t)s * HID);              \
        float e;                                                        \
        e = ex2(v.x * t2); den.x += e; num.x = fmaf(v.x, e, num.x);     \
        e = ex2(v.y * t2); den.y += e; num.y = fmaf(v.y, e, num.y);     \
        e = ex2(v.z * t2); den.z += e; num.z = fmaf(v.z, e, num.z);     \
        e = ex2(v.w * t2); den.w += e; num.w = fmaf(v.w, e, num.w);     \
    }
    for (; k + 8 <= end; k += 8) { STEP64(k) STEP64(k + 2) STEP64(k + 4) STEP64(k + 6) }
    for (; k + 2 <= end; k += 2) STEP64(k)
#undef STEP64
    if (k < end) {  // masked tail step (1 edge; half 1 masked out)
        int kk = min(k + h, end - 1);
        int s = g_csr[kk];
        float m = (k + h < end) ? 1.f : 0.f;
        float4 v = *(const float4*)(xb + (size_t)s * HID);
        float e;
        e = ex2(v.x * t2) * m; den.x += e; num.x = fmaf(v.x, e, num.x);
        e = ex2(v.y * t2) * m; den.y += e; num.y = fmaf(v.y, e, num.y);
        e = ex2(v.z * t2) * m; den.z += e; num.z = fmaf(v.z, e, num.z);
        e = ex2(v.w * t2) * m; den.w += e; num.w = fmaf(v.w, e, num.w);
    }
    // reduce across the 2 halves
    num.x += __shfl_xor_sync(0xFFFFFFFFu, num.x, 16);
    num.y += __shfl_xor_sync(0xFFFFFFFFu, num.y, 16);
    num.z += __shfl_xor_sync(0xFFFFFFFFu, num.z, 16);
    num.w += __shfl_xor_sync(0xFFFFFFFFu, num.w, 16);
    den.x += __shfl_xor_sync(0xFFFFFFFFu, den.x, 16);
    den.y += __shfl_xor_sync(0xFFFFFFFFu, den.y, 16);
    den.z += __shfl_xor_sync(0xFFFFFFFFu, den.z, 16);
    den.w += __shfl_xor_sync(0xFFFFFFFFu, den.w, 16);
    if (lane < 16) {
        float4 o;
        o.x = (den.x > 0.f) ? num.x / den.x : 0.f;
        o.y = (den.y > 0.f) ? num.y / den.y : 0.f;
        o.z = (den.z > 0.f) ? num.z / den.z : 0.f;
        o.w = (den.w > 0.f) ? num.w / den.w : 0.f;
        *(float4*)(aggr + (size_t)node * HID + cl) = o;
    }
}

// ---------------- fused dual-GEMM + instance-norm + relu + per-graph segmax -----------
// r15 ncu: regs=104 -> 2 CTAs/SM (21.5% occ), issue 29.5% -> latency-bound.
// REGISTER DIET: 4 nodes/thread (acc 16 regs, int row offsets), grid x2.
// Mainloop math identical (pk2+ffma2); batched segmax over the 4-node run.
template <int C, int CREAL>
__global__ __launch_bounds__(256) void k_lin(const float* __restrict__ xin,
                                             const float* __restrict__ aggr,
                                             const float* __restrict__ Wr,
                                             const float* __restrict__ br,
                                             const float* __restrict__ Ws,
                                             const int* __restrict__ batch,
                                             int loff,
                                             float* __restrict__ y) {
    __shared__ __align__(16) float sWr[C * HID];  // [c][o]
    __shared__ __align__(16) float sWs[C * HID];  // [c][o]
    __shared__ __align__(16) float sb[HID];
    int tid = threadIdx.x;
    for (int i = tid; i < C * HID; i += 256) {
        int o = i / C, c = i % C;
        float wr = (c < CREAL) ? Wr[o * CREAL + c] : 0.f;
        float ws = (c < CREAL) ? Ws[o * CREAL + c] : 0.f;
        sWr[c * HID + o] = wr;
        sWs[c * HID + o] = ws;
    }
    if (tid < HID) sb[tid] = br[tid];
    __syncthreads();

    int oq = tid & 15;
    int ng = tid >> 4;
    int o0 = oq * 4;
    int n0 = blockIdx.x * 64 + ng * 4;

    int rowoff[4];
#pragma unroll
    for (int n = 0; n < 4; n++) {
        int node = n0 + n;
        if (node >= N_NODES) node = N_NODES - 1;
        rowoff[n] = node * C;
    }

    ulonglong2 b2 = *(const ulonglong2*)&sb[o0];
    u64 accA[4], accB[4];
#pragma unroll
    for (int n = 0; n < 4; n++) { accA[n] = b2.x; accB[n] = b2.y; }

    for (int c = 0; c < C; c += 4) {
        ulonglong2 wr0 = *(const ulonglong2*)&sWr[(c + 0) * HID + o0];
        ulonglong2 wr1 = *(const ulonglong2*)&sWr[(c + 1) * HID + o0];
        ulonglong2 wr2 = *(const ulonglong2*)&sWr[(c + 2) * HID + o0];
        ulonglong2 wr3 = *(const ulonglong2*)&sWr[(c + 3) * HID + o0];
        ulonglong2 ws0 = *(const ulonglong2*)&sWs[(c + 0) * HID + o0];
        ulonglong2 ws1 = *(const ulonglong2*)&sWs[(c + 1) * HID + o0];
        ulonglong2 ws2 = *(const ulonglong2*)&sWs[(c + 2) * HID + o0];
        ulonglong2 ws3 = *(const ulonglong2*)&sWs[(c + 3) * HID + o0];
#pragma unroll
        for (int n = 0; n < 4; n++) {
            float4 av = *(const float4*)(aggr + rowoff[n] + c);
            float4 xv = *(const float4*)(xin + rowoff[n] + c);
            u64 p;
            p = pk2(av.x); accA[n] = ffma2(p, wr0.x, accA[n]); accB[n] = ffma2(p, wr0.y, accB[n]);
            p = pk2(xv.x); accA[n] = ffma2(p, ws0.x, accA[n]); accB[n] = ffma2(p, ws0.y, accB[n]);
            p = pk2(av.y); accA[n] = ffma2(p, wr1.x, accA[n]); accB[n] = ffma2(p, wr1.y, accB[n]);
            p = pk2(xv.y); accA[n] = ffma2(p, ws1.x, accA[n]); accB[n] = ffma2(p, ws1.y, accB[n]);
            p = pk2(av.z); accA[n] = ffma2(p, wr2.x, accA[n]); accB[n] = ffma2(p, wr2.y, accB[n]);
            p = pk2(xv.z); accA[n] = ffma2(p, ws2.x, accA[n]); accB[n] = ffma2(p, ws2.y, accB[n]);
            p = pk2(av.w); accA[n] = ffma2(p, wr3.x, accA[n]); accB[n] = ffma2(p, wr3.y, accB[n]);
            p = pk2(xv.w); accA[n] = ffma2(p, ws3.x, accA[n]); accB[n] = ffma2(p, ws3.y, accB[n]);
        }
    }

    // epilogue: instance norm (16-lane group) + relu + store + batched segmax
    float4 gm = make_float4(0.f, 0.f, 0.f, 0.f);
    int curg = -1;
#pragma unroll
    for (int n = 0; n < 4; n++) {
        int node = n0 + n;
        if (node >= N_NODES) break;  // uniform across the 16-lane group
        float2 p0 = up2(accA[n]);
        float2 p1 = up2(accB[n]);
        float sum = p0.x + p0.y + p1.x + p1.y;
#pragma unroll
        for (int off = 8; off; off >>= 1) sum += __shfl_xor_sync(0xFFFFFFFFu, sum, off);
        float mu = sum * (1.0f / HID);
        float d0 = p0.x - mu, d1 = p0.y - mu, d2 = p1.x - mu, d3 = p1.y - mu;
        float q = d0 * d0 + d1 * d1 + d2 * d2 + d3 * d3;
#pragma unroll
        for (int off = 8; off; off >>= 1) q += __shfl_xor_sync(0xFFFFFFFFu, q, off);
        float r = rsqrtf(q * (1.0f / HID) + EPS_IN);
        float4 o;
        o.x = fmaxf(d0 * r, 0.f);
        o.y = fmaxf(d1 * r, 0.f);
        o.z = fmaxf(d2 * r, 0.f);
        o.w = fmaxf(d3 * r, 0.f);
        *(float4*)&y[(size_t)node * HID + o0] = o;
        int g = __ldg(&batch[node]);
        if (g != curg) {
            if (curg >= 0) {
                unsigned* hrow = g_hbits + curg * (3 * HID) + loff + o0;
                atomicMax(&hrow[0], __float_as_uint(gm.x));
                atomicMax(&hrow[1], __float_as_uint(gm.y));
                atomicMax(&hrow[2], __float_as_uint(gm.z));
                atomicMax(&hrow[3], __float_as_uint(gm.w));
            }
            curg = g;
            gm = o;
        } else {
            gm.x = fmaxf(gm.x, o.x);
            gm.y = fmaxf(gm.y, o.y);
            gm.z = fmaxf(gm.z, o.z);
            gm.w = fmaxf(gm.w, o.w);
        }
    }
    if (curg >= 0) {
        unsigned* hrow = g_hbits + curg * (3 * HID) + loff + o0;
        atomicMax(&hrow[0], __float_as_uint(gm.x));
        atomicMax(&hrow[1], __float_as_uint(gm.y));
        atomicMax(&hrow[2], __float_as_uint(gm.z));
        atomicMax(&hrow[3], __float_as_uint(gm.w));
    }
}

// ---------------- head MLP: one block per graph ----------------
__global__ __launch_bounds__(192) void k_final(const float* __restrict__ bl1,
                                               const float* __restrict__ bl2,
                                               float* __restrict__ out) {
    __shared__ float sh[3 * HID];
    __shared__ float sz1[2 * HID];
    __shared__ float sz2[HID / 2];
    int g = blockIdx.x;
    int tid = threadIdx.x;
    sh[tid] = __uint_as_float(g_hbits[g * (3 * HID) + tid]);
    __syncthreads();
    if (tid < 2 * HID) {
        float acc = bl1[tid];
#pragma unroll 4
        for (int c = 0; c < 3 * HID; c++) acc += sh[c] * g_Wl1T[c * (2 * HID) + tid];
        sz1[tid] = fmaxf(acc, 0.f);
    }
    __syncthreads();
    if (tid < HID / 2) {
        float acc = bl2[tid];
#pragma unroll 4
        for (int c = 0; c < 2 * HID; c++) acc += sz1[c] * g_Wl2T[c * (HID / 2) + tid];
        sz2[tid] = acc;
    }
    __syncthreads();
    if (tid < 32) {
        float v = sz2[tid];
        float q = v * v;
#pragma unroll
        for (int o = 16; o; o >>= 1) q += __shfl_xor_sync(0xFFFFFFFFu, q, o);
        float nrm = fmaxf(sqrtf(q), 1e-12f);
        out[g * 32 + tid] = v / nrm;
    }
}

// ---------------- launch ----------------
extern "C" void kernel_launch(void* const* d_in, const int* in_sizes, int n_in,
                              void* d_out, int out_size) {
    const float* x = (const float*)d_in[0];
    const int* ei = (const int*)d_in[1];
    const int* src = ei;
    const int* dst = ei + N_EDGES;
    const int* batch = (const int*)d_in[2];
    const float* t = (const float*)d_in[3];
    const float* W1r = (const float*)d_in[4];
    const float* b1 = (const float*)d_in[5];
    const float* W1s = (const float*)d_in[6];
    const float* W2r = (const float*)d_in[7];
    const float* b2 = (const float*)d_in[8];
    const float* W2s = (const float*)d_in[9];
    const float* W3r = (const float*)d_in[10];
    const float* b3 = (const float*)d_in[11];
    const float* W3s = (const float*)d_in[12];
    const float* Wl1 = (const float*)d_in[13];
    const float* bl1 = (const float*)d_in[14];
    const float* Wl2 = (const float*)d_in[15];
    const float* bl2 = (const float*)d_in[16];
    float* out = (float*)d_out;

    float *xpad, *bufA, *bufB, *aggr;
    cudaGetSymbolAddress((void**)&xpad, g_xpad);
    cudaGetSymbolAddress((void**)&bufA, g_bufA);
    cudaGetSymbolAddress((void**)&bufB, g_bufB);
    cudaGetSymbolAddress((void**)&aggr, g_aggr);

    const int PB = (N_NODES * C_PAD + 255) / 256;  // 6250 (covers hist range too)
    const int E4B = (E4 + 255) / 256;              // 782
    const int WB = (N_NODES * 32 + 255) / 256;     // warp-per-node: 6250
    const int LB = (N_NODES + 63) / 64;            // 782 (4 nodes/thread)

    k_prep<<<PB, 256>>>(x, Wl1, Wl2, dst);  // pad + zero + transpose + hist
    k_scan<<<SCAN_NB, SCAN_B>>>();          // fused reduce+barrier+scan; re-zeroes g_deg
    k_scatter<<<E4B, 256>>>(src, dst);

    // layer 1 (padded to 32 ch; channel 31 is exactly zero everywhere)
    k_aggr32<<<WB, 256>>>(xpad, t, aggr);
    k_lin<C_PAD, IN_CH><<<LB, 256>>>(xpad, aggr, W1r, b1, W1s, batch, 0, bufA);

    // layer 2
    k_aggr64<<<WB, 256>>>(bufA, t, aggr);
    k_lin<HID, HID><<<LB, 256>>>(bufA, aggr, W2r, b2, W2s, batch, HID, bufB);

    // layer 3
    k_aggr64<<<WB, 256>>>(bufB, t, aggr);
    k_lin<HID, HID><<<LB, 256>>>(bufB, aggr, W3r, b3, W3s, batch, 2 * HID, bufA);

    k_final<<<N_GRAPHS, 192>>>(bl1, bl2, out);
    (void)in_sizes; (void)n_in; (void)out_size;
}

// round 17
// speedup vs baseline: 1.1940x; 1.1940x over previous
#include <cuda_runtime.h>
#include <cstdint>

#define N_NODES 50000
#define N_EDGES 800000
#define N_GRAPHS 128
#define IN_CH 31
#define C_PAD 32
#define HID 64
#define EPS_IN 1e-5f
#define LOG2E 1.4426950408889634f

#define SCAN_B 1024
#define SCAN_NB ((N_NODES + SCAN_B - 1) / SCAN_B)  // 49
#define E4 (N_EDGES / 4)                            // 200000

typedef unsigned long long u64;

// ---------------- scratch (static device globals; no allocation) ----------------
// INVARIANT: g_deg is all-zero at every kernel_launch entry (zero-init at module
// load; k_scan re-zeroes it after consuming it each run). g_syncc is zeroed by
// k_prep before k_scan uses it.
__device__ float g_xpad[N_NODES * C_PAD];
__device__ float g_bufA[N_NODES * HID];
__device__ float g_bufB[N_NODES * HID];
__device__ float g_aggr[N_NODES * HID];
__device__ int g_deg[N_NODES];
__device__ int g_rowptr[N_NODES + 1];
__device__ int g_fill[N_NODES];
__device__ int g_csr[N_EDGES];
__device__ int g_part[SCAN_NB];
__device__ int g_syncc;
__device__ unsigned g_hbits[N_GRAPHS * 3 * HID];
__device__ float g_Wl1T[(3 * HID) * (2 * HID)];
__device__ float g_Wl2T[(2 * HID) * (HID / 2)];

// ---------------- packed / fast-math helpers ----------------
__device__ __forceinline__ u64 pk2(float v) {
    u64 r;
    asm("mov.b64 %0, {%1, %1};" : "=l"(r) : "f"(v));
    return r;
}
__device__ __forceinline__ u64 ffma2(u64 a, u64 b, u64 c) {
    u64 d;
    asm("fma.rn.f32x2 %0, %1, %2, %3;" : "=l"(d) : "l"(a), "l"(b), "l"(c));
    return d;
}
__device__ __forceinline__ float2 up2(u64 v) {
    float2 f;
    asm("mov.b64 {%0, %1}, %2;" : "=f"(f.x), "=f"(f.y) : "l"(v));
    return f;
}
__device__ __forceinline__ float ex2(float x) {
    float r;
    asm("ex2.approx.f32 %0, %1;" : "=f"(r) : "f"(x));
    return r;
}
// approx reciprocal (MUFU.RCP, rel err ~2^-22): replaces the ~14-instr IEEE
// divide sequence in the issue-bound aggr epilogues.
__device__ __forceinline__ float frcp(float x) {
    float r;
    asm("rcp.approx.f32 %0, %1;" : "=f"(r) : "f"(x));
    return r;
}

// ---------------- prep: pad x, zero hbits/sync, transpose head weights, AND hist ----
__global__ void k_prep(const float* __restrict__ x,
                       const float* __restrict__ Wl1,
                       const float* __restrict__ Wl2,
                       const int* __restrict__ dst) {
    int i = blockIdx.x * 256 + threadIdx.x;
    if (i == 0) g_syncc = 0;
    if (i < N_NODES * C_PAD) {
        int n = i >> 5, c = i & 31;
        g_xpad[i] = (c < IN_CH) ? x[n * IN_CH + c] : 0.f;
    }
    if (i < N_GRAPHS * 3 * HID / 4) {
        ((uint4*)g_hbits)[i] = make_uint4(0u, 0u, 0u, 0u);
    }
    if (i < 128 * 192) {
        int o = i / 192, c = i % 192;
        g_Wl1T[c * 128 + o] = Wl1[i];
    }
    if (i < 32 * 128) {
        int o = i / 128, c = i % 128;
        g_Wl2T[c * 32 + o] = Wl2[i];
    }
    if (i < E4) {
        int4 d = __ldg((const int4*)dst + i);
        atomicAdd(&g_deg[d.x], 1);
        atomicAdd(&g_deg[d.y], 1);
        atomicAdd(&g_deg[d.z], 1);
        atomicAdd(&g_deg[d.w], 1);
    }
}

// ---------------- single-kernel exclusive scan with software global barrier --------
// 49 blocks x 1024 threads: always co-resident on 148 SMs -> spin is safe.
__global__ void k_scan() {
    __shared__ int ws[32];
    __shared__ int soff_sh;
    int tid = threadIdx.x;
    int b = blockIdx.x;
    int lane = tid & 31, w = tid >> 5;
    int i = b * SCAN_B + tid;
    int v = (i < N_NODES) ? g_deg[i] : 0;

    // phase A: block reduce
    int r = v;
#pragma unroll
    for (int off = 16; off; off >>= 1) r += __shfl_xor_sync(0xFFFFFFFFu, r, off);
    if (lane == 0) ws[w] = r;
    __syncthreads();
    if (tid < 32) {
        int u = ws[tid];
#pragma unroll
        for (int off = 16; off; off >>= 1) u += __shfl_xor_sync(0xFFFFFFFFu, u, off);
        if (tid == 0) {
            g_part[b] = u;
            __threadfence();
            atomicAdd(&g_syncc, 1);
        }
    }
    if (tid == 0) soff_sh = 0;
    if (tid == 0) {
        while (*(volatile int*)&g_syncc < SCAN_NB) {}
    }
    __syncthreads();
    __threadfence();

    // phase B: sum of g_part[0..b-1]
    if (tid < 64) {
        int pv = (tid < b) ? g_part[tid] : 0;  // b <= 48 < 64
#pragma unroll
        for (int off = 16; off; off >>= 1) pv += __shfl_xor_sync(0xFFFFFFFFu, pv, off);
        if (lane == 0) atomicAdd(&soff_sh, pv);
    }

    // phase C: block scan (warp shfl)
    int sc = v;
#pragma unroll
    for (int off = 1; off < 32; off <<= 1) {
        int a = __shfl_up_sync(0xFFFFFFFFu, sc, off);
        if (lane >= off) sc += a;
    }
    if (lane == 31) ws[w] = sc;
    __syncthreads();
    if (tid < 32) {
        int u = ws[tid];
#pragma unroll
        for (int off = 1; off < 32; off <<= 1) {
            int a = __shfl_up_sync(0xFFFFFFFFu, u, off);
            if (tid >= off) u += a;
        }
        ws[tid] = u;
    }
    __syncthreads();
    int woff = (w > 0) ? ws[w - 1] : 0;
    if (i < N_NODES) {
        int incl = sc + woff + soff_sh;
        g_rowptr[i + 1] = incl;
        g_fill[i] = incl - v;
        g_deg[i] = 0;  // restore invariant for next run's fused hist
    }
    if (b == 0 && tid == 0) g_rowptr[0] = 0;
}

// separate scatter: 200K threads -> max ATOMG concurrency (proven; the 49-block
// fused variant regressed in r15)
__global__ void k_scatter(const int* __restrict__ src, const int* __restrict__ dst) {
    int e4 = blockIdx.x * 256 + threadIdx.x;
    if (e4 < E4) {
        int4 d = __ldg((const int4*)dst + e4);
        int4 sv = __ldg((const int4*)src + e4);
        int p0 = atomicAdd(&g_fill[d.x], 1);
        int p1 = atomicAdd(&g_fill[d.y], 1);
        int p2 = atomicAdd(&g_fill[d.z], 1);
        int p3 = atomicAdd(&g_fill[d.w], 1);
        g_csr[p0] = sv.x;
        g_csr[p1] = sv.y;
        g_csr[p2] = sv.z;
        g_csr[p3] = sv.w;
    }
}

// ---------------- one-pass segment softmax aggregation ----------------
// aggr[n,c] = sum_e v*exp(t*v) / sum_e exp(t*v)  (shift-invariant; logits bounded)
// aggr32: quarter-warp edge-parallel — 4 edges/step, 8 lanes per edge, float4/lane.
__global__ __launch_bounds__(256) void k_aggr32(const float* __restrict__ xin,
                                                const float* __restrict__ tptr,
                                                float* __restrict__ aggr) {
    int node = (blockIdx.x * 256 + threadIdx.x) >> 5;
    int lane = threadIdx.x & 31;
    if (node >= N_NODES) return;
    float t2 = __ldg(tptr) * LOG2E;
    int beg = g_rowptr[node];
    int end = g_rowptr[node + 1];
    int q = lane >> 3;        // quarter 0..3 -> edge k+q
    int cl = (lane & 7) * 4;  // channels cl..cl+3
    const float* xb = xin + cl;
    float4 num = make_float4(0.f, 0.f, 0.f, 0.f);
    float4 den = make_float4(0.f, 0.f, 0.f, 0.f);
    int k = beg;
#define STEP32(kk)                                                      \
    {                                                                   \
        int s = g_csr[(kk) + q];                                        \
        float4 v = *(const float4*)(xb + (size_t)s * C_PAD);            \
        float e;                                                        \
        e = ex2(v.x * t2); den.x += e; num.x = fmaf(v.x, e, num.x);     \
        e = ex2(v.y * t2); den.y += e; num.y = fmaf(v.y, e, num.y);     \
        e = ex2(v.z * t2); den.z += e; num.z = fmaf(v.z, e, num.z);     \
        e = ex2(v.w * t2); den.w += e; num.w = fmaf(v.w, e, num.w);     \
    }
    for (; k + 8 <= end; k += 8) { STEP32(k) STEP32(k + 4) }
    for (; k + 4 <= end; k += 4) STEP32(k)
#undef STEP32
    if (k < end) {  // masked tail step (1..3 edges)
        int kk = min(k + q, end - 1);
        int s = g_csr[kk];
        float m = (k + q < end) ? 1.f : 0.f;
        float4 v = *(const float4*)(xb + (size_t)s * C_PAD);
        float e;
        e = ex2(v.x * t2) * m; den.x += e; num.x = fmaf(v.x, e, num.x);
        e = ex2(v.y * t2) * m; den.y += e; num.y = fmaf(v.y, e, num.y);
        e = ex2(v.z * t2) * m; den.z += e; num.z = fmaf(v.z, e, num.z);
        e = ex2(v.w * t2) * m; den.w += e; num.w = fmaf(v.w, e, num.w);
    }
    // reduce across the 4 quarters (channel set identical per lane&7)
#pragma unroll
    for (int off = 8; off <= 16; off <<= 1) {
        num.x += __shfl_xor_sync(0xFFFFFFFFu, num.x, off);
        num.y += __shfl_xor_sync(0xFFFFFFFFu, num.y, off);
        num.z += __shfl_xor_sync(0xFFFFFFFFu, num.z, off);
        num.w += __shfl_xor_sync(0xFFFFFFFFu, num.w, off);
        den.x += __shfl_xor_sync(0xFFFFFFFFu, den.x, off);
        den.y += __shfl_xor_sync(0xFFFFFFFFu, den.y, off);
        den.z += __shfl_xor_sync(0xFFFFFFFFu, den.z, off);
        den.w += __shfl_xor_sync(0xFFFFFFFFu, den.w, off);
    }
    if (lane < 8) {
        float4 o;
        o.x = (den.x > 0.f) ? num.x * frcp(den.x) : 0.f;
        o.y = (den.y > 0.f) ? num.y * frcp(den.y) : 0.f;
        o.z = (den.z > 0.f) ? num.z * frcp(den.z) : 0.f;
        o.w = (den.w > 0.f) ? num.w * frcp(den.w) : 0.f;
        *(float4*)(aggr + (size_t)node * C_PAD + cl) = o;
    }
}

// aggr64: half-warp edge-parallel — 2 edges/step, 16 lanes per edge, float4/lane.
__global__ __launch_bounds__(256) void k_aggr64(const float* __restrict__ xin,
                                                const float* __restrict__ tptr,
                                                float* __restrict__ aggr) {
    int node = (blockIdx.x * 256 + threadIdx.x) >> 5;
    int lane = threadIdx.x & 31;
    if (node >= N_NODES) return;
    float t2 = __ldg(tptr) * LOG2E;
    int beg = g_rowptr[node];
    int end = g_rowptr[node + 1];
    int h = lane >> 4;         // half 0/1 -> edge k+h
    int cl = (lane & 15) * 4;  // channels cl..cl+3
    const float* xb = xin + cl;
    float4 num = make_float4(0.f, 0.f, 0.f, 0.f);
    float4 den = make_float4(0.f, 0.f, 0.f, 0.f);
    int k = beg;
#define STEP64(kk)                                                      \
    {                                                                   \
        int s = g_csr[(kk) + h];                                        \
        float4 v = *(const float4*)(xb + (size_t)s * HID);              \
        float e;                                                        \
        e = ex2(v.x * t2); den.x += e; num.x = fmaf(v.x, e, num.x);     \
        e = ex2(v.y * t2); den.y += e; num.y = fmaf(v.y, e, num.y);     \
        e = ex2(v.z * t2); den.z += e; num.z = fmaf(v.z, e, num.z);     \
        e = ex2(v.w * t2); den.w += e; num.w = fmaf(v.w, e, num.w);     \
    }
    for (; k + 8 <= end; k += 8) { STEP64(k) STEP64(k + 2) STEP64(k + 4) STEP64(k + 6) }
    for (; k + 2 <= end; k += 2) STEP64(k)
#undef STEP64
    if (k < end) {  // masked tail step (1 edge; half 1 masked out)
        int kk = min(k + h, end - 1);
        int s = g_csr[kk];
        float m = (k + h < end) ? 1.f : 0.f;
        float4 v = *(const float4*)(xb + (size_t)s * HID);
        float e;
        e = ex2(v.x * t2) * m; den.x += e; num.x = fmaf(v.x, e, num.x);
        e = ex2(v.y * t2) * m; den.y += e; num.y = fmaf(v.y, e, num.y);
        e = ex2(v.z * t2) * m; den.z += e; num.z = fmaf(v.z, e, num.z);
        e = ex2(v.w * t2) * m; den.w += e; num.w = fmaf(v.w, e, num.w);
    }
    // reduce across the 2 halves
    num.x += __shfl_xor_sync(0xFFFFFFFFu, num.x, 16);
    num.y += __shfl_xor_sync(0xFFFFFFFFu, num.y, 16);
    num.z += __shfl_xor_sync(0xFFFFFFFFu, num.z, 16);
    num.w += __shfl_xor_sync(0xFFFFFFFFu, num.w, 16);
    den.x += __shfl_xor_sync(0xFFFFFFFFu, den.x, 16);
    den.y += __shfl_xor_sync(0xFFFFFFFFu, den.y, 16);
    den.z += __shfl_xor_sync(0xFFFFFFFFu, den.z, 16);
    den.w += __shfl_xor_sync(0xFFFFFFFFu, den.w, 16);
    if (lane < 16) {
        float4 o;
        o.x = (den.x > 0.f) ? num.x * frcp(den.x) : 0.f;
        o.y = (den.y > 0.f) ? num.y * frcp(den.y) : 0.f;
        o.z = (den.z > 0.f) ? num.z * frcp(den.z) : 0.f;
        o.w = (den.w > 0.f) ? num.w * frcp(den.w) : 0.f;
        *(float4*)(aggr + (size_t)node * HID + cl) = o;
    }
}

// ---------------- fused dual-GEMM + instance-norm + relu + per-graph segmax -----------
// PROVEN form (r9-r13, 236us): 16 o-quads x 16 node-groups of 8 nodes, pk2+ffma2
// mainloop, batched segmax epilogue. DO NOT restructure (r8/r15/r16 all regressed).
template <int C, int CREAL>
__global__ __launch_bounds__(256) void k_lin(const float* __restrict__ xin,
                                             const float* __restrict__ aggr,
                                             const float* __restrict__ Wr,
                                             const float* __restrict__ br,
                                             const float* __restrict__ Ws,
                                             const int* __restrict__ batch,
                                             int loff,
                                             float* __restrict__ y) {
    __shared__ __align__(16) float sWr[C * HID];  // [c][o]
    __shared__ __align__(16) float sWs[C * HID];  // [c][o]
    __shared__ __align__(16) float sb[HID];
    int tid = threadIdx.x;
    for (int i = tid; i < C * HID; i += 256) {
        int o = i / C, c = i % C;
        float wr = (c < CREAL) ? Wr[o * CREAL + c] : 0.f;
        float ws = (c < CREAL) ? Ws[o * CREAL + c] : 0.f;
        sWr[c * HID + o] = wr;
        sWs[c * HID + o] = ws;
    }
    if (tid < HID) sb[tid] = br[tid];
    __syncthreads();

    int oq = tid & 15;
    int ng = tid >> 4;
    int o0 = oq * 4;
    int n0 = blockIdx.x * 128 + ng * 8;

    size_t rowoff[8];
#pragma unroll
    for (int n = 0; n < 8; n++) {
        int node = n0 + n;
        if (node >= N_NODES) node = N_NODES - 1;
        rowoff[n] = (size_t)node * C;
    }

    ulonglong2 b2 = *(const ulonglong2*)&sb[o0];
    u64 accA[8], accB[8];
#pragma unroll
    for (int n = 0; n < 8; n++) { accA[n] = b2.x; accB[n] = b2.y; }

    for (int c = 0; c < C; c += 4) {
        ulonglong2 wr0 = *(const ulonglong2*)&sWr[(c + 0) * HID + o0];
        ulonglong2 wr1 = *(const ulonglong2*)&sWr[(c + 1) * HID + o0];
        ulonglong2 wr2 = *(const ulonglong2*)&sWr[(c + 2) * HID + o0];
        ulonglong2 wr3 = *(const ulonglong2*)&sWr[(c + 3) * HID + o0];
        ulonglong2 ws0 = *(const ulonglong2*)&sWs[(c + 0) * HID + o0];
        ulonglong2 ws1 = *(const ulonglong2*)&sWs[(c + 1) * HID + o0];
        ulonglong2 ws2 = *(const ulonglong2*)&sWs[(c + 2) * HID + o0];
        ulonglong2 ws3 = *(const ulonglong2*)&sWs[(c + 3) * HID + o0];
#pragma unroll
        for (int n = 0; n < 8; n++) {
            float4 av = *(const float4*)(aggr + rowoff[n] + c);
            float4 xv = *(const float4*)(xin + rowoff[n] + c);
            u64 p;
            p = pk2(av.x); accA[n] = ffma2(p, wr0.x, accA[n]); accB[n] = ffma2(p, wr0.y, accB[n]);
            p = pk2(xv.x); accA[n] = ffma2(p, ws0.x, accA[n]); accB[n] = ffma2(p, ws0.y, accB[n]);
            p = pk2(av.y); accA[n] = ffma2(p, wr1.x, accA[n]); accB[n] = ffma2(p, wr1.y, accB[n]);
            p = pk2(xv.y); accA[n] = ffma2(p, ws1.x, accA[n]); accB[n] = ffma2(p, ws1.y, accB[n]);
            p = pk2(av.z); accA[n] = ffma2(p, wr2.x, accA[n]); accB[n] = ffma2(p, wr2.y, accB[n]);
            p = pk2(xv.z); accA[n] = ffma2(p, ws2.x, accA[n]); accB[n] = ffma2(p, ws2.y, accB[n]);
            p = pk2(av.w); accA[n] = ffma2(p, wr3.x, accA[n]); accB[n] = ffma2(p, wr3.y, accB[n]);
            p = pk2(xv.w); accA[n] = ffma2(p, ws3.x, accA[n]); accB[n] = ffma2(p, ws3.y, accB[n]);
        }
    }

    // epilogue: instance norm (16-lane group) + relu + store + batched segmax
    float4 gm = make_float4(0.f, 0.f, 0.f, 0.f);
    int curg = -1;
#pragma unroll
    for (int n = 0; n < 8; n++) {
        int node = n0 + n;
        if (node >= N_NODES) break;  // uniform across the 16-lane group
        float2 p0 = up2(accA[n]);
        float2 p1 = up2(accB[n]);
        float sum = p0.x + p0.y + p1.x + p1.y;
#pragma unroll
        for (int off = 8; off; off >>= 1) sum += __shfl_xor_sync(0xFFFFFFFFu, sum, off);
        float mu = sum * (1.0f / HID);
        float d0 = p0.x - mu, d1 = p0.y - mu, d2 = p1.x - mu, d3 = p1.y - mu;
        float q = d0 * d0 + d1 * d1 + d2 * d2 + d3 * d3;
#pragma unroll
        for (int off = 8; off; off >>= 1) q += __shfl_xor_sync(0xFFFFFFFFu, q, off);
        float r = rsqrtf(q * (1.0f / HID) + EPS_IN);
        float4 o;
        o.x = fmaxf(d0 * r, 0.f);
        o.y = fmaxf(d1 * r, 0.f);
        o.z = fmaxf(d2 * r, 0.f);
        o.w = fmaxf(d3 * r, 0.f);
        *(float4*)&y[(size_t)node * HID + o0] = o;
        int g = __ldg(&batch[node]);
        if (g != curg) {
            if (curg >= 0) {
                unsigned* hrow = g_hbits + curg * (3 * HID) + loff + o0;
                atomicMax(&hrow[0], __float_as_uint(gm.x));
                atomicMax(&hrow[1], __float_as_uint(gm.y));
                atomicMax(&hrow[2], __float_as_uint(gm.z));
                atomicMax(&hrow[3], __float_as_uint(gm.w));
            }
            curg = g;
            gm = o;
        } else {
            gm.x = fmaxf(gm.x, o.x);
            gm.y = fmaxf(gm.y, o.y);
            gm.z = fmaxf(gm.z, o.z);
            gm.w = fmaxf(gm.w, o.w);
        }
    }
    if (curg >= 0) {
        unsigned* hrow = g_hbits + curg * (3 * HID) + loff + o0;
        atomicMax(&hrow[0], __float_as_uint(gm.x));
        atomicMax(&hrow[1], __float_as_uint(gm.y));
        atomicMax(&hrow[2], __float_as_uint(gm.z));
        atomicMax(&hrow[3], __float_as_uint(gm.w));
    }
}

// ---------------- head MLP: one block per graph ----------------
__global__ __launch_bounds__(192) void k_final(const float* __restrict__ bl1,
                                               const float* __restrict__ bl2,
                                               float* __restrict__ out) {
    __shared__ float sh[3 * HID];
    __shared__ float sz1[2 * HID];
    __shared__ float sz2[HID / 2];
    int g = blockIdx.x;
    int tid = threadIdx.x;
    sh[tid] = __uint_as_float(g_hbits[g * (3 * HID) + tid]);
    __syncthreads();
    if (tid < 2 * HID) {
        float acc = bl1[tid];
#pragma unroll 4
        for (int c = 0; c < 3 * HID; c++) acc += sh[c] * g_Wl1T[c * (2 * HID) + tid];
        sz1[tid] = fmaxf(acc, 0.f);
    }
    __syncthreads();
    if (tid < HID / 2) {
        float acc = bl2[tid];
#pragma unroll 4
        for (int c = 0; c < 2 * HID; c++) acc += sz1[c] * g_Wl2T[c * (HID / 2) + tid];
        sz2[tid] = acc;
    }
    __syncthreads();
    if (tid < 32) {
        float v = sz2[tid];
        float q = v * v;
#pragma unroll
        for (int o = 16; o; o >>= 1) q += __shfl_xor_sync(0xFFFFFFFFu, q, o);
        float nrm = fmaxf(sqrtf(q), 1e-12f);
        out[g * 32 + tid] = v / nrm;
    }
}

// ---------------- launch ----------------
extern "C" void kernel_launch(void* const* d_in, const int* in_sizes, int n_in,
                              void* d_out, int out_size) {
    const float* x = (const float*)d_in[0];
    const int* ei = (const int*)d_in[1];
    const int* src = ei;
    const int* dst = ei + N_EDGES;
    const int* batch = (const int*)d_in[2];
    const float* t = (const float*)d_in[3];
    const float* W1r = (const float*)d_in[4];
    const float* b1 = (const float*)d_in[5];
    const float* W1s = (const float*)d_in[6];
    const float* W2r = (const float*)d_in[7];
    const float* b2 = (const float*)d_in[8];
    const float* W2s = (const float*)d_in[9];
    const float* W3r = (const float*)d_in[10];
    const float* b3 = (const float*)d_in[11];
    const float* W3s = (const float*)d_in[12];
    const float* Wl1 = (const float*)d_in[13];
    const float* bl1 = (const float*)d_in[14];
    const float* Wl2 = (const float*)d_in[15];
    const float* bl2 = (const float*)d_in[16];
    float* out = (float*)d_out;

    float *xpad, *bufA, *bufB, *aggr;
    cudaGetSymbolAddress((void**)&xpad, g_xpad);
    cudaGetSymbolAddress((void**)&bufA, g_bufA);
    cudaGetSymbolAddress((void**)&bufB, g_bufB);
    cudaGetSymbolAddress((void**)&aggr, g_aggr);

    const int PB = (N_NODES * C_PAD + 255) / 256;  // 6250 (covers hist range too)
    const int E4B = (E4 + 255) / 256;              // 782
    const int WB = (N_NODES * 32 + 255) / 256;     // warp-per-node: 6250
    const int LB = (N_NODES + 127) / 128;          // 391 (8 nodes/thread, PROVEN)

    k_prep<<<PB, 256>>>(x, Wl1, Wl2, dst);  // pad + zero + transpose + hist
    k_scan<<<SCAN_NB, SCAN_B>>>();          // fused reduce+barrier+scan; re-zeroes g_deg
    k_scatter<<<E4B, 256>>>(src, dst);

    // layer 1 (padded to 32 ch; channel 31 is exactly zero everywhere)
    k_aggr32<<<WB, 256>>>(xpad, t, aggr);
    k_lin<C_PAD, IN_CH><<<LB, 256>>>(xpad, aggr, W1r, b1, W1s, batch, 0, bufA);

    // layer 2
    k_aggr64<<<WB, 256>>>(bufA, t, aggr);
    k_lin<HID, HID><<<LB, 256>>>(bufA, aggr, W2r, b2, W2s, batch, HID, bufB);

    // layer 3
    k_aggr64<<<WB, 256>>>(bufB, t, aggr);
    k_lin<HID, HID><<<LB, 256>>>(bufB, aggr, W3r, b3, W3s, batch, 2 * HID, bufA);

    k_final<<<N_GRAPHS, 192>>>(bl1, bl2, out);
    (void)in_sizes; (void)n_in; (void)out_size;
}